// round 15
// baseline (speedup 1.0000x reference)
#include <cuda_runtime.h>
#include <cuda_bf16.h>
#include <mma.h>
#include <cstdint>
#include <cstddef>

using namespace nvcuda;

// Problem constants
#define BATCH 8
#define NQ 1024
#define NKV 1024
#define DMODEL 512
#define NH 8
#define DH 64
#define BH (BATCH*NH)          // 64
#define SCALE 0.125f           // DH^-0.5

// Scratch (allocation-free rule: __device__ globals)
__device__ float g_Q[(size_t)BH*NQ*DH];     // [bh][q][d]
__device__ float g_K[(size_t)BH*NKV*DH];    // [bh][k][d]
__device__ float g_V[(size_t)BH*NKV*DH];    // [bh][k][d]
__device__ float g_ctx[(size_t)BATCH*NQ*DMODEL]; // [b][q][h*64+d]
__device__ float g_scores_fallback[(size_t)BH*NQ*NKV]; // only if out buffer lacks attn region

// split one float4 into bf16 hi + lo pairs (4 consecutive halfs each)
__device__ __forceinline__ void cvt_split4(float4 v, __nv_bfloat16* hp, __nv_bfloat16* lp)
{
    __nv_bfloat16 h0 = __float2bfloat16(v.x), h1 = __float2bfloat16(v.y);
    __nv_bfloat16 h2 = __float2bfloat16(v.z), h3 = __float2bfloat16(v.w);
    __nv_bfloat162 p0; p0.x = h0; p0.y = h1;
    __nv_bfloat162 p1; p1.x = h2; p1.y = h3;
    *(__nv_bfloat162*)(hp)     = p0;
    *(__nv_bfloat162*)(hp + 2) = p1;
    __nv_bfloat162 l0, l1;
    l0.x = __float2bfloat16(v.x - __bfloat162float(h0));
    l0.y = __float2bfloat16(v.y - __bfloat162float(h1));
    l1.x = __float2bfloat16(v.z - __bfloat162float(h2));
    l1.y = __float2bfloat16(v.w - __bfloat162float(h3));
    *(__nv_bfloat162*)(lp)     = l0;
    *(__nv_bfloat162*)(lp + 2) = l1;
}

// ===========================================================================
// WMMA SGEMM (split-bf16 x3): C[8192,512] = A[8192,512] @ W[512,512] + bias
// Tile 64x128, BK=32, 256 thr (8 warps), warp tile 32x32, 2 CTAs/SM.
// ===========================================================================
#define SG_LDA 48    // halfs
#define SG_LDB 144   // halfs
#define SG_AHI 0
#define SG_ALO 6144
#define SG_BHI 12288
#define SG_BLO 21504
#define SG_STG_LD 136  // floats
#define SG_SMEM 34816

__global__ __launch_bounds__(256, 2) void sgemm_wmma_kernel(
    const float* __restrict__ A, const float* __restrict__ W,
    const float* __restrict__ bias, float* __restrict__ C, int permute)
{
    extern __shared__ __align__(256) char sm[];
    __nv_bfloat16* Ahi = (__nv_bfloat16*)(sm + SG_AHI);
    __nv_bfloat16* Alo = (__nv_bfloat16*)(sm + SG_ALO);
    __nv_bfloat16* Bhi = (__nv_bfloat16*)(sm + SG_BHI);
    __nv_bfloat16* Blo = (__nv_bfloat16*)(sm + SG_BLO);
    float* stg = (float*)sm;

    const int tid = threadIdx.x;
    const int wid = tid >> 5;
    const int wm = wid >> 2;       // 0..1: 32-row slab
    const int wn = wid & 3;        // 0..3: 32-col slab
    const int row0 = blockIdx.y * 64;
    const int col0 = blockIdx.x * 128;

    wmma::fragment<wmma::accumulator, 16, 16, 16, float> acc[2][2];
    #pragma unroll
    for (int i = 0; i < 2; i++)
        #pragma unroll
        for (int j = 0; j < 2; j++)
            wmma::fill_fragment(acc[i][j], 0.f);

    for (int k0 = 0; k0 < DMODEL; k0 += 32) {
        #pragma unroll
        for (int i = 0; i < 2; i++) {
            int s = tid + i * 256;
            int r = s >> 3;
            int c4 = (s & 7) * 4;
            float4 v = *(const float4*)&A[(size_t)(row0 + r) * DMODEL + k0 + c4];
            cvt_split4(v, &Ahi[r * SG_LDA + c4], &Alo[r * SG_LDA + c4]);
        }
        #pragma unroll
        for (int i = 0; i < 4; i++) {
            int s = tid + i * 256;
            int r = s >> 5;
            int c4 = (s & 31) * 4;
            float4 v = *(const float4*)&W[(size_t)(k0 + r) * DMODEL + col0 + c4];
            cvt_split4(v, &Bhi[r * SG_LDB + c4], &Blo[r * SG_LDB + c4]);
        }
        __syncthreads();

        #pragma unroll
        for (int ks = 0; ks < 32; ks += 16) {
            wmma::fragment<wmma::matrix_a, 16,16,16, __nv_bfloat16, wmma::row_major> ah[2], al[2];
            wmma::fragment<wmma::matrix_b, 16,16,16, __nv_bfloat16, wmma::row_major> bh2[2], bl2[2];
            #pragma unroll
            for (int i = 0; i < 2; i++) {
                int m0 = wm * 32 + i * 16;
                wmma::load_matrix_sync(ah[i], &Ahi[m0 * SG_LDA + ks], SG_LDA);
                wmma::load_matrix_sync(al[i], &Alo[m0 * SG_LDA + ks], SG_LDA);
            }
            #pragma unroll
            for (int j = 0; j < 2; j++) {
                int n0 = wn * 32 + j * 16;
                wmma::load_matrix_sync(bh2[j], &Bhi[ks * SG_LDB + n0], SG_LDB);
                wmma::load_matrix_sync(bl2[j], &Blo[ks * SG_LDB + n0], SG_LDB);
            }
            #pragma unroll
            for (int i = 0; i < 2; i++)
                #pragma unroll
                for (int j = 0; j < 2; j++) {
                    wmma::mma_sync(acc[i][j], ah[i], bh2[j], acc[i][j]);
                    wmma::mma_sync(acc[i][j], al[i], bh2[j], acc[i][j]);
                    wmma::mma_sync(acc[i][j], ah[i], bl2[j], acc[i][j]);
                }
        }
        __syncthreads();
    }

    #pragma unroll
    for (int i = 0; i < 2; i++)
        #pragma unroll
        for (int j = 0; j < 2; j++)
            wmma::store_matrix_sync(
                &stg[(wm * 32 + i * 16) * SG_STG_LD + wn * 32 + j * 16],
                acc[i][j], SG_STG_LD, wmma::mem_row_major);
    __syncthreads();

    #pragma unroll
    for (int i = 0; i < 8; i++) {
        int s = tid + i * 256;
        int r = s >> 5;
        int c4 = (s & 31) * 4;
        float4 v = *(float4*)&stg[r * SG_STG_LD + c4];
        int gc = col0 + c4;
        v.x += bias[gc]; v.y += bias[gc + 1]; v.z += bias[gc + 2]; v.w += bias[gc + 3];
        int gr = row0 + r;
        if (permute) {
            int b = gr >> 10, n = gr & 1023;
            int h = gc >> 6,  d = gc & 63;
            *(float4*)&C[(((size_t)(b * NH + h)) * NQ + n) * DH + d] = v;
        } else {
            *(float4*)&C[(size_t)gr * DMODEL + gc] = v;
        }
    }
}

// ===========================================================================
// WMMA QK^T (split-bf16 x3): S[bh][q][k] = sum_d Q[bh][q][d]*K[bh][k][d]
// Tile 64(q)x128(k), full d=64 staged once, 256 thr, warp 32x32, 2 CTAs/SM.
// ===========================================================================
#define QK_LD 80     // halfs (d=64 padded)
#define QK_QHI 0
#define QK_QLO 10240
#define QK_KHI 20480
#define QK_KLO 40960
#define QK_SMEM 61440

__global__ __launch_bounds__(256, 2) void qk_wmma_kernel(
    const float* __restrict__ Q, const float* __restrict__ Km,
    float* __restrict__ S)
{
    extern __shared__ __align__(256) char sm[];
    __nv_bfloat16* Qhi = (__nv_bfloat16*)(sm + QK_QHI);
    __nv_bfloat16* Qlo = (__nv_bfloat16*)(sm + QK_QLO);
    __nv_bfloat16* Khi = (__nv_bfloat16*)(sm + QK_KHI);
    __nv_bfloat16* Klo = (__nv_bfloat16*)(sm + QK_KLO);

    const int bh = blockIdx.z;
    const int q0 = blockIdx.y * 64;
    const int k0 = blockIdx.x * 128;
    const float* Qb = Q + (size_t)bh * NQ * DH;
    const float* Kb = Km + (size_t)bh * NKV * DH;

    const int tid = threadIdx.x;
    const int wid = tid >> 5;
    const int wm = wid >> 2;   // 0..1: 32-q slab
    const int wn = wid & 3;    // 0..3: 32-k slab

    #pragma unroll
    for (int i = 0; i < 4; i++) {
        int s = tid + i * 256;
        int r = s >> 4;
        int c4 = (s & 15) * 4;
        float4 v = *(const float4*)&Qb[(size_t)(q0 + r) * DH + c4];
        cvt_split4(v, &Qhi[r * QK_LD + c4], &Qlo[r * QK_LD + c4]);
    }
    #pragma unroll
    for (int i = 0; i < 8; i++) {
        int s = tid + i * 256;
        int r = s >> 4;
        int c4 = (s & 15) * 4;
        float4 w = *(const float4*)&Kb[(size_t)(k0 + r) * DH + c4];
        cvt_split4(w, &Khi[r * QK_LD + c4], &Klo[r * QK_LD + c4]);
    }
    __syncthreads();

    wmma::fragment<wmma::accumulator, 16, 16, 16, float> acc[2][2];
    #pragma unroll
    for (int i = 0; i < 2; i++)
        #pragma unroll
        for (int j = 0; j < 2; j++)
            wmma::fill_fragment(acc[i][j], 0.f);

    #pragma unroll
    for (int ks = 0; ks < DH; ks += 16) {
        wmma::fragment<wmma::matrix_a, 16,16,16, __nv_bfloat16, wmma::row_major> ah[2], al[2];
        wmma::fragment<wmma::matrix_b, 16,16,16, __nv_bfloat16, wmma::col_major> bh2[2], bl2[2];
        #pragma unroll
        for (int i = 0; i < 2; i++) {
            int m0 = wm * 32 + i * 16;
            wmma::load_matrix_sync(ah[i], &Qhi[m0 * QK_LD + ks], QK_LD);
            wmma::load_matrix_sync(al[i], &Qlo[m0 * QK_LD + ks], QK_LD);
        }
        #pragma unroll
        for (int j = 0; j < 2; j++) {
            int n0 = wn * 32 + j * 16;
            wmma::load_matrix_sync(bh2[j], &Khi[n0 * QK_LD + ks], QK_LD);
            wmma::load_matrix_sync(bl2[j], &Klo[n0 * QK_LD + ks], QK_LD);
        }
        #pragma unroll
        for (int i = 0; i < 2; i++)
            #pragma unroll
            for (int j = 0; j < 2; j++) {
                wmma::mma_sync(acc[i][j], ah[i], bh2[j], acc[i][j]);
                wmma::mma_sync(acc[i][j], al[i], bh2[j], acc[i][j]);
                wmma::mma_sync(acc[i][j], ah[i], bl2[j], acc[i][j]);
            }
    }

    #pragma unroll
    for (int i = 0; i < 2; i++)
        #pragma unroll
        for (int j = 0; j < 2; j++)
            wmma::store_matrix_sync(
                &S[((size_t)bh * NQ + q0 + wm * 32 + i * 16) * NKV + k0 + wn * 32 + j * 16],
                acc[i][j], NKV, wmma::mem_row_major);
}

// ===========================================================================
// FUSED RPE + scale + mask + softmax:
//   S[bh][q][:] = softmax_k( mask ? (S1 + Q·R)·scale : -inf )
// Block per (bh-half of 32, q). Score slab 32x1024 held in f32 smem.
// WMMA bias (M=32 bh x N=128 k x K=64 d) accumulated straight into the slab,
// then one gmem read of S1 combines, then in-smem softmax writes attn.
// R is read 2x total (once per half). 256 thr, warp tile 16x32.
// ===========================================================================
#define FS_LD 80                       // halfs
#define FS_S    0                      // f32 [32][1024] = 131072 B
#define FS_QHI  131072                 // 32*80*2 = 5120
#define FS_QLO  136192
#define FS_RHI  141312                 // 128*80*2 = 20480
#define FS_RLO  161792
#define FS_MSK  182272                 // 4096 ints = 16384 B
#define FS_SMEM 198656

__global__ __launch_bounds__(256) void rpe_softmax_kernel(
    const float* __restrict__ Q, const float* __restrict__ R,
    const int* __restrict__ mask, float* __restrict__ S)
{
    extern __shared__ __align__(256) char sm[];
    float* Ssm = (float*)(sm + FS_S);              // [32][1024]
    __nv_bfloat16* Qhi = (__nv_bfloat16*)(sm + FS_QHI);
    __nv_bfloat16* Qlo = (__nv_bfloat16*)(sm + FS_QLO);
    __nv_bfloat16* Rhi = (__nv_bfloat16*)(sm + FS_RHI);
    __nv_bfloat16* Rlo = (__nv_bfloat16*)(sm + FS_RLO);
    int* msk = (int*)(sm + FS_MSK);                // [4][1024]

    const int half = blockIdx.x;       // 0/1
    const int q    = blockIdx.y;
    const int bh0  = half * 32;
    const int tid  = threadIdx.x;
    const int wid  = tid >> 5;
    const int lane = tid & 31;
    const int wm   = wid >> 2;         // 0..1: 16-row slab
    const int wn   = wid & 3;          // 0..3: 32-col slab

    // mask rows b = half*4 .. half*4+3 (4096 ints, 16/thread)
    #pragma unroll
    for (int i = 0; i < 16; i++) {
        int s = tid + i * 256;
        msk[s] = mask[(size_t)(half * 4 + (s >> 10)) * NKV + (s & 1023)];
    }
    // Q tile: 32 bh x 64 d (strided gather at row q), 512 f4, 2/thread
    #pragma unroll
    for (int i = 0; i < 2; i++) {
        int s = tid + i * 256;
        int r = s >> 4;
        int c4 = (s & 15) * 4;
        float4 v = *(const float4*)&Q[(((size_t)(bh0 + r) * NQ) + q) * DH + c4];
        cvt_split4(v, &Qhi[r * FS_LD + c4], &Qlo[r * FS_LD + c4]);
    }
    __syncthreads();

    // bias GEMM per k-tile of 128, accumulators stored straight into Ssm
    #pragma unroll 1
    for (int kt = 0; kt < 8; kt++) {
        const int k0 = kt * 128;
        if (kt > 0) __syncthreads();   // prior tile's frag loads done before R overwrite
        #pragma unroll
        for (int i = 0; i < 8; i++) {
            int s = tid + i * 256;
            int r = s >> 4;
            int c4 = (s & 15) * 4;
            float4 w = *(const float4*)&R[(((size_t)q * NKV) + k0 + r) * DH + c4];
            cvt_split4(w, &Rhi[r * FS_LD + c4], &Rlo[r * FS_LD + c4]);
        }
        __syncthreads();

        wmma::fragment<wmma::accumulator, 16, 16, 16, float> acc[2];
        wmma::fill_fragment(acc[0], 0.f);
        wmma::fill_fragment(acc[1], 0.f);

        #pragma unroll
        for (int ks = 0; ks < 64; ks += 16) {
            wmma::fragment<wmma::matrix_a, 16,16,16, __nv_bfloat16, wmma::row_major> ah, al;
            wmma::fragment<wmma::matrix_b, 16,16,16, __nv_bfloat16, wmma::col_major> bh2[2], bl2[2];
            wmma::load_matrix_sync(ah, &Qhi[(wm * 16) * FS_LD + ks], FS_LD);
            wmma::load_matrix_sync(al, &Qlo[(wm * 16) * FS_LD + ks], FS_LD);
            #pragma unroll
            for (int j = 0; j < 2; j++) {
                int n0 = wn * 32 + j * 16;
                wmma::load_matrix_sync(bh2[j], &Rhi[n0 * FS_LD + ks], FS_LD);
                wmma::load_matrix_sync(bl2[j], &Rlo[n0 * FS_LD + ks], FS_LD);
            }
            #pragma unroll
            for (int j = 0; j < 2; j++) {
                wmma::mma_sync(acc[j], ah, bh2[j], acc[j]);
                wmma::mma_sync(acc[j], al, bh2[j], acc[j]);
                wmma::mma_sync(acc[j], ah, bl2[j], acc[j]);
            }
        }
        #pragma unroll
        for (int j = 0; j < 2; j++)
            wmma::store_matrix_sync(
                &Ssm[(wm * 16) * NKV + k0 + wn * 32 + j * 16],
                acc[j], NKV, wmma::mem_row_major);
    }
    __syncthreads();

    // combine with S1 from gmem: add + scale + mask (8192 f4, 32/thread)
    #pragma unroll
    for (int i = 0; i < 32; i++) {
        int s = tid + i * 256;
        int r = s >> 8;               // 0..31
        int c4 = (s & 255) * 4;       // k
        size_t base = (((size_t)(bh0 + r)) * NQ + q) * NKV + c4;
        float4 sv = *(const float4*)&S[base];
        float4 bv = *(float4*)&Ssm[r * NKV + c4];
        int bl = r >> 3;              // local b 0..3
        float4 ov;
        ov.x = (msk[bl * 1024 + c4 + 0] != 0) ? (sv.x + bv.x) * SCALE : -1e30f;
        ov.y = (msk[bl * 1024 + c4 + 1] != 0) ? (sv.y + bv.y) * SCALE : -1e30f;
        ov.z = (msk[bl * 1024 + c4 + 2] != 0) ? (sv.z + bv.z) * SCALE : -1e30f;
        ov.w = (msk[bl * 1024 + c4 + 3] != 0) ? (sv.w + bv.w) * SCALE : -1e30f;
        *(float4*)&Ssm[r * NKV + c4] = ov;
    }
    __syncthreads();

    // softmax: warp wid handles rows wid*4 .. wid*4+3; write attn to gmem
    #pragma unroll
    for (int rr = 0; rr < 4; rr++) {
        int r = wid * 4 + rr;
        float* row = &Ssm[r * NKV];
        float4 v[8];
        float m = -3e38f;
        #pragma unroll
        for (int j = 0; j < 8; j++) {
            v[j] = *(float4*)&row[(j * 32 + lane) * 4];
            m = fmaxf(m, fmaxf(fmaxf(v[j].x, v[j].y), fmaxf(v[j].z, v[j].w)));
        }
        #pragma unroll
        for (int o = 16; o > 0; o >>= 1)
            m = fmaxf(m, __shfl_xor_sync(0xFFFFFFFFu, m, o));
        float sum = 0.f;
        #pragma unroll
        for (int j = 0; j < 8; j++) {
            v[j].x = __expf(v[j].x - m); v[j].y = __expf(v[j].y - m);
            v[j].z = __expf(v[j].z - m); v[j].w = __expf(v[j].w - m);
            sum += v[j].x + v[j].y + v[j].z + v[j].w;
        }
        #pragma unroll
        for (int o = 16; o > 0; o >>= 1)
            sum += __shfl_xor_sync(0xFFFFFFFFu, sum, o);
        float inv = 1.f / sum;
        float* grow = &S[(((size_t)(bh0 + r)) * NQ + q) * NKV];
        #pragma unroll
        for (int j = 0; j < 8; j++) {
            float4 o4 = make_float4(v[j].x * inv, v[j].y * inv, v[j].z * inv, v[j].w * inv);
            *(float4*)&grow[(j * 32 + lane) * 4] = o4;
        }
    }
}

// ===========================================================================
// WMMA PV (split-bf16 x3) — unchanged
// ===========================================================================
#define PV_LD 80
#define PV_PHI 0
#define PV_PLO 20480
#define PV_VHI 40960
#define PV_VLO 51200
#define PV_SMEM 61440

__global__ __launch_bounds__(256) void pv_wmma_kernel(
    const float* __restrict__ P, const float* __restrict__ V,
    float* __restrict__ ctx)
{
    extern __shared__ __align__(256) char sm[];
    __nv_bfloat16* Phi = (__nv_bfloat16*)(sm + PV_PHI);
    __nv_bfloat16* Plo = (__nv_bfloat16*)(sm + PV_PLO);
    __nv_bfloat16* Vhi = (__nv_bfloat16*)(sm + PV_VHI);
    __nv_bfloat16* Vlo = (__nv_bfloat16*)(sm + PV_VLO);

    const int bh = blockIdx.y;
    const int q0 = blockIdx.x * 128;
    const float* Pb = P + (size_t)bh * NQ * NKV;
    const float* Vb = V + (size_t)bh * NKV * DH;

    const int tid = threadIdx.x;
    const int wid = tid >> 5;
    const int wm = wid >> 1;   // 0..3: 32-q slab
    const int wn = wid & 1;    // 0..1: 32-d slab

    wmma::fragment<wmma::accumulator, 16, 16, 16, float> acc[2][2];
    #pragma unroll
    for (int i = 0; i < 2; i++)
        #pragma unroll
        for (int j = 0; j < 2; j++)
            wmma::fill_fragment(acc[i][j], 0.f);

    #pragma unroll 1
    for (int k0 = 0; k0 < NKV; k0 += 64) {
        #pragma unroll
        for (int i = 0; i < 8; i++) {
            int s = tid + i * 256;
            int r = s >> 4;
            int c4 = (s & 15) * 4;
            float4 v = *(const float4*)&Pb[(size_t)(q0 + r) * NKV + k0 + c4];
            cvt_split4(v, &Phi[r * PV_LD + c4], &Plo[r * PV_LD + c4]);
        }
        #pragma unroll
        for (int i = 0; i < 4; i++) {
            int s = tid + i * 256;
            int r = s >> 4;
            int c4 = (s & 15) * 4;
            float4 w = *(const float4*)&Vb[(size_t)(k0 + r) * DH + c4];
            cvt_split4(w, &Vhi[r * PV_LD + c4], &Vlo[r * PV_LD + c4]);
        }
        __syncthreads();

        #pragma unroll
        for (int ks = 0; ks < 64; ks += 16) {
            wmma::fragment<wmma::matrix_a, 16,16,16, __nv_bfloat16, wmma::row_major> ah[2], al[2];
            wmma::fragment<wmma::matrix_b, 16,16,16, __nv_bfloat16, wmma::row_major> bh2[2], bl2[2];
            #pragma unroll
            for (int i = 0; i < 2; i++) {
                int m0 = wm * 32 + i * 16;
                wmma::load_matrix_sync(ah[i], &Phi[m0 * PV_LD + ks], PV_LD);
                wmma::load_matrix_sync(al[i], &Plo[m0 * PV_LD + ks], PV_LD);
            }
            #pragma unroll
            for (int j = 0; j < 2; j++) {
                int n0 = wn * 32 + j * 16;
                wmma::load_matrix_sync(bh2[j], &Vhi[ks * PV_LD + n0], PV_LD);
                wmma::load_matrix_sync(bl2[j], &Vlo[ks * PV_LD + n0], PV_LD);
            }
            #pragma unroll
            for (int i = 0; i < 2; i++)
                #pragma unroll
                for (int j = 0; j < 2; j++) {
                    wmma::mma_sync(acc[i][j], ah[i], bh2[j], acc[i][j]);
                    wmma::mma_sync(acc[i][j], al[i], bh2[j], acc[i][j]);
                    wmma::mma_sync(acc[i][j], ah[i], bl2[j], acc[i][j]);
                }
        }
        __syncthreads();
    }

    const int b = bh >> 3, h = bh & 7;
    #pragma unroll
    for (int i = 0; i < 2; i++)
        #pragma unroll
        for (int j = 0; j < 2; j++) {
            int qq = q0 + wm * 32 + i * 16;
            int dd = h * DH + wn * 32 + j * 16;
            wmma::store_matrix_sync(
                &ctx[((size_t)(b * NQ + qq)) * DMODEL + dd],
                acc[i][j], DMODEL, wmma::mem_row_major);
        }
}

// ---------------------------------------------------------------------------
extern "C" void kernel_launch(void* const* d_in, const int* in_sizes, int n_in,
                              void* d_out, int out_size)
{
    const float* q    = (const float*)d_in[0];
    const float* kv   = (const float*)d_in[1];
    const int*   mask = (const int*)  d_in[2];
    const float* Wq   = (const float*)d_in[3];
    const float* bq   = (const float*)d_in[4];
    const float* Wk   = (const float*)d_in[5];
    const float* bk   = (const float*)d_in[6];
    const float* Wv   = (const float*)d_in[7];
    const float* bv   = (const float*)d_in[8];
    const float* Wo   = (const float*)d_in[9];
    const float* bo   = (const float*)d_in[10];
    const float* R    = (const float*)d_in[11];

    float* out = (float*)d_out;
    const size_t out_elems  = (size_t)BATCH * NQ * DMODEL;       // 4,194,304
    const size_t attn_elems = (size_t)BH * NQ * NKV;             // 67,108,864

    static float *Qp = nullptr, *Kp = nullptr, *Vp = nullptr, *ctx = nullptr, *fb = nullptr;
    if (!Qp) {
        cudaGetSymbolAddress((void**)&Qp,  g_Q);
        cudaGetSymbolAddress((void**)&Kp,  g_K);
        cudaGetSymbolAddress((void**)&Vp,  g_V);
        cudaGetSymbolAddress((void**)&ctx, g_ctx);
        cudaGetSymbolAddress((void**)&fb,  g_scores_fallback);
        cudaFuncSetAttribute(sgemm_wmma_kernel,
                             cudaFuncAttributeMaxDynamicSharedMemorySize, SG_SMEM);
        cudaFuncSetAttribute(qk_wmma_kernel,
                             cudaFuncAttributeMaxDynamicSharedMemorySize, QK_SMEM);
        cudaFuncSetAttribute(rpe_softmax_kernel,
                             cudaFuncAttributeMaxDynamicSharedMemorySize, FS_SMEM);
        cudaFuncSetAttribute(pv_wmma_kernel,
                             cudaFuncAttributeMaxDynamicSharedMemorySize, PV_SMEM);
    }

    float* scores = ((size_t)out_size >= out_elems + attn_elems) ? (out + out_elems) : fb;

    const int M = BATCH * NQ;   // 8192
    dim3 gemm_grid(DMODEL / 128, M / 64);   // (4, 128)

    // 1-3: projections (WMMA split-bf16) with [b,h,n,d] permuted store
    sgemm_wmma_kernel<<<gemm_grid, 256, SG_SMEM>>>(q,  Wq, bq, Qp, 1);
    sgemm_wmma_kernel<<<gemm_grid, 256, SG_SMEM>>>(kv, Wk, bk, Kp, 1);
    sgemm_wmma_kernel<<<gemm_grid, 256, SG_SMEM>>>(kv, Wv, bv, Vp, 1);

    // 4: S1 = Q K^T per bh (WMMA, 64x128 tiles, 2 CTAs/SM)
    dim3 qk_grid(NKV / 128, NQ / 64, BH);   // (8,16,64)
    qk_wmma_kernel<<<qk_grid, 256, QK_SMEM>>>(Qp, Kp, scores);

    // 5+6 fused: attn = softmax(mask ? (S1 + Q·R)*scale : -inf)
    dim3 fs_grid(2, NQ);                    // (2,1024)
    rpe_softmax_kernel<<<fs_grid, 256, FS_SMEM>>>(Qp, R, mask, scores);

    // 7: ctx = attn @ V (WMMA), stored [b,q,h*64+d]
    dim3 pv_grid(NQ / 128, BH);             // (8,64)
    pv_wmma_kernel<<<pv_grid, 256, PV_SMEM>>>(scores, Vp, ctx);

    // 8: out = ctx @ Wo + bo (WMMA)
    sgemm_wmma_kernel<<<gemm_grid, 256, SG_SMEM>>>(ctx, Wo, bo, out, 0);
}